// round 13
// baseline (speedup 1.0000x reference)
#include <cuda_runtime.h>
#include <math.h>

#define BB 4
#define CC 8
#define HH 256
#define WW 256
#define INF_D 512
#define JT 8                          // columns per colin tile
#define NR 8                          // rows per colin thread (interleaved)
#define JTO 2                         // columns per colout tile
#define NRO 2                         // rows per colout thread
#define NIN   (BB*CC*(WW/JT))         // 1024 colin blocks
#define NOUT  (BB*(WW/JTO))           // 512 colout blocks
#define NCOL  (NIN + NOUT)            // 1536 k_col blocks
#define NROWB (BB*HH)                 // 1024 rowpass blocks
#define NSMB  ((BB*HH*WW)/(4*256))    // 256 softmax blocks (float4, 256 thr)

// Static device scratch (no allocations allowed). All zero-initialized at
// module load; k_col's last block restores g_cnt/g_sem to 0 every launch,
// so graph replays see identical initial state.
__device__ unsigned short g_gin[BB*CC*HH*WW];   // 4 MB: per-class row distance (inside)
__device__ unsigned short g_tr[BB*HH*WW];       // 0.5 MB: packed (t<<10 | r)
__device__ float          g_prob[BB*CC*HH*WW];  // 8 MB: softmax probabilities
__device__ int            g_cnt[BB*CC];         // class presence counts
__device__ float          g_part[NCOL];         // block partial sums
__device__ int            g_sem;                // arrival counter

// ---------------------------------------------------------------------------
// Nearest set bit distance in a 256-bit mask (8 words), bits optionally
// inverted by xor with `inv`. Returns 0 if bit j itself is set; INF_D if none.
__device__ __forceinline__ int nearest_bit(const unsigned* wd, unsigned inv, int j) {
    const int wj = j >> 5, bj = j & 31;
    const unsigned cur = wd[wj] ^ inv;
    int dl = INF_D, dr = INF_D;

    unsigned m = cur & (0xffffffffu >> (31 - bj));   // bits [0..bj]
    if (m) {
        dl = bj - (31 - __clz(m));
    } else {
        #pragma unroll
        for (int w = 6; w >= 0; --w) {
            if (w < wj) {
                const unsigned mw = wd[w] ^ inv;
                if (mw) { dl = j - (w*32 + 31 - __clz(mw)); break; }
            }
        }
    }
    m = cur >> bj;                                   // bits [bj..31]
    if (m) {
        dr = __ffs(m) - 1;
    } else {
        #pragma unroll
        for (int w = 1; w <= 7; ++w) {
            if (w > wj) {
                const unsigned mw = wd[w] ^ inv;
                if (mw) { dr = (w*32 + __ffs(mw) - 1) - j; break; }
            }
        }
    }
    int d = dl < dr ? dl : dr;
    return d < INF_D ? d : INF_D;
}

// Pre-pass: blocks [0, NROWB) run the bitmask row pass; blocks
// [NROWB, NROWB+NSMB) run float4 softmax. Independent work, one launch.
__global__ void k_pre(const int* __restrict__ target,
                      const float* __restrict__ output) {
    if (blockIdx.x < NROWB) {
        // ---------------- row pass ----------------
        const int row = blockIdx.x;          // b*HH + h
        const int b   = row >> 8;
        const int h   = row & 255;
        const int j   = threadIdx.x;
        const int w   = j >> 5;
        const int ln  = j & 31;

        __shared__ unsigned mask[CC][8];
        const int t = target[row * WW + j];

        #pragma unroll
        for (int c = 0; c < CC; ++c) {
            const unsigned m = __ballot_sync(0xffffffffu, t == c);
            if (ln == 0) mask[c][w] = m;
        }
        __syncthreads();

        const int r = nearest_bit(mask[t], 0xffffffffu, j);
        g_tr[row * WW + j] = (unsigned short)(r | (t << 10));

        #pragma unroll
        for (int c = 0; c < CC; ++c) {
            const int g = nearest_bit(mask[c], 0u, j);
            g_gin[((b*CC + c)*HH + h)*WW + j] = (unsigned short)g;
        }

        if (j < CC) {
            int cnt = 0;
            #pragma unroll
            for (int k = 0; k < 8; ++k) cnt += __popc(mask[j][k]);
            if (cnt) atomicAdd(&g_cnt[b*CC + j], cnt);
        }
    } else {
        // ---------------- softmax (float4) ----------------
        const int q   = (blockIdx.x - NROWB) * 256 + threadIdx.x; // 0..65535
        const int b   = q >> 14;
        const int hw4 = q & 16383;
        const float4* out4 = (const float4*)output;
        float4* prob4 = (float4*)g_prob;

        float4 lg[CC];
        float mx = -1e30f, my = -1e30f, mz = -1e30f, mw = -1e30f;
        #pragma unroll
        for (int c = 0; c < CC; ++c) {
            lg[c] = out4[(b*CC + c)*16384 + hw4];
            mx = fmaxf(mx, lg[c].x); my = fmaxf(my, lg[c].y);
            mz = fmaxf(mz, lg[c].z); mw = fmaxf(mw, lg[c].w);
        }
        float sx = 0.f, sy = 0.f, sz = 0.f, sw = 0.f;
        #pragma unroll
        for (int c = 0; c < CC; ++c) {
            lg[c].x = __expf(lg[c].x - mx); sx += lg[c].x;
            lg[c].y = __expf(lg[c].y - my); sy += lg[c].y;
            lg[c].z = __expf(lg[c].z - mz); sz += lg[c].z;
            lg[c].w = __expf(lg[c].w - mw); sw += lg[c].w;
        }
        const float ix = 1.f/sx, iy = 1.f/sy, iz = 1.f/sz, iw = 1.f/sw;
        #pragma unroll
        for (int c = 0; c < CC; ++c)
            prob4[(b*CC + c)*16384 + hw4] =
                make_float4(lg[c].x*ix, lg[c].y*iy, lg[c].z*iz, lg[c].w*iw);
    }
}

// Deterministic block reduce into *dst (thread 0 writes).
__device__ __forceinline__ void block_reduce_write(float acc, float* dst) {
    #pragma unroll
    for (int o = 16; o > 0; o >>= 1)
        acc += __shfl_xor_sync(0xffffffffu, acc, o);
    __shared__ float swarp[8];
    if ((threadIdx.x & 31) == 0) swarp[threadIdx.x >> 5] = acc;
    __syncthreads();
    if (threadIdx.x == 0) {
        float s0 = 0.f;
        #pragma unroll
        for (int w = 0; w < 8; ++w) s0 += swarp[w];
        *dst = s0;
    }
}

// Merged column pass + last-block final reduction.
// Blocks [0, NIN): inside transform. Blocks [NIN, NCOL): collapsed outside.
// Every block writes one partial and arrives on g_sem; the last arrival
// sums all partials (fixed order -> deterministic), writes the result, and
// resets g_cnt / g_sem for the next graph replay.
__global__ void k_col(float* __restrict__ out) {
    __shared__ float s[HH*JT];                  // 8 KB, aliased by both paths
    float acc = 0.0f;

    if (blockIdx.x < NIN) {
        // ---------------- inside transform ----------------
        const int jt  = blockIdx.x & (WW/JT - 1);
        const int bc  = blockIdx.x / (WW/JT);
        const int j0  = jt * JT;

        if (g_cnt[bc] != 0) {
            const int jj = threadIdx.x & (JT - 1);
            const int k0 = threadIdx.x / JT;    // 0..31

            #pragma unroll
            for (int m = 0; m < NR; ++m) {
                const int k = k0 + 32*m;
                const float g = (float)g_gin[(bc*HH + k)*WW + j0 + jj];
                s[k*JT + jj] = g * g;
            }
            __syncthreads();

            float din2[NR], vlo[NR], vhi[NR];
            #pragma unroll
            for (int r = 0; r < NR; ++r) {
                const int i = k0 + 32*r;
                din2[r] = s[i*JT + jj];
                vlo[r]  = (i-1 >= 0) ? s[(i-1)*JT + jj] : 1e9f;
                vhi[r]  = (i+1 < HH) ? s[(i+1)*JT + jj] : 1e9f;
            }
            float mx = 0.f;
            #pragma unroll
            for (int r = 0; r < NR; ++r) mx = fmaxf(mx, din2[r]);

            for (int d = 1; d < HH; ++d) {
                const float dd2 = (float)(d * d);
                if (dd2 >= mx) break;
                #pragma unroll
                for (int r = 0; r < NR; ++r)
                    din2[r] = fminf(din2[r], dd2 + fminf(vlo[r], vhi[r]));
                #pragma unroll
                for (int r = 0; r < NR; ++r) {  // prefetch step d+1
                    const int i  = k0 + 32*r;
                    const int lo = i - d - 1, hi = i + d + 1;
                    vlo[r] = (lo >= 0) ? s[lo*JT + jj] : 1e9f;
                    vhi[r] = (hi < HH) ? s[hi*JT + jj] : 1e9f;
                }
                mx = 0.f;
                #pragma unroll
                for (int r = 0; r < NR; ++r) mx = fmaxf(mx, din2[r]);
            }

            #pragma unroll
            for (int r = 0; r < NR; ++r) {
                const int i = k0 + 32*r;
                acc += sqrtf(din2[r]) * g_prob[(bc*HH + i)*WW + j0 + jj];
            }
        }
    } else {
        // ------------- outside transform (collapsed) -------------
        const int bid = blockIdx.x - NIN;       // 0..511
        const int jt  = bid & (WW/JTO - 1);     // 0..127
        const int b   = bid / (WW/JTO);
        const int j0  = jt * JTO;

        int* si = (int*)s;
        const int jj = threadIdx.x & (JTO - 1); // 0..1
        const int k0 = threadIdx.x / JTO;       // 0..127

        #pragma unroll
        for (int m = 0; m < NRO; ++m) {
            const int k = k0 + 128*m;
            const unsigned v = g_tr[(b*HH + k)*WW + j0 + jj];
            const int rr = (int)(v & 1023u);
            si[k*JTO + jj] = (rr*rr*8) | (int)(v >> 10);   // r^2<<3 | t
        }
        __syncthreads();

        float dout2[NRO];
        int   tc[NRO], plo[NRO], phi[NRO];
        #pragma unroll
        for (int r = 0; r < NRO; ++r) {
            const int i  = k0 + 128*r;
            const int pv = si[i*JTO + jj];
            tc[r]    = pv & 7;
            dout2[r] = (float)(pv >> 3);
            plo[r]   = (i-1 >= 0) ? si[(i-1)*JTO + jj] : -1;
            phi[r]   = (i+1 < HH) ? si[(i+1)*JTO + jj] : -1;
        }
        float mx = 0.f;
        #pragma unroll
        for (int r = 0; r < NRO; ++r) mx = fmaxf(mx, dout2[r]);

        for (int d = 1; d < HH; ++d) {
            const float dd2 = (float)(d * d);
            if (dd2 >= mx) break;
            #pragma unroll
            for (int r = 0; r < NRO; ++r) {
                const float vl = (plo[r] < 0) ? 1e9f
                               : (((plo[r] & 7) == tc[r]) ? (float)(plo[r] >> 3) : 0.0f);
                const float vh = (phi[r] < 0) ? 1e9f
                               : (((phi[r] & 7) == tc[r]) ? (float)(phi[r] >> 3) : 0.0f);
                dout2[r] = fminf(dout2[r], dd2 + fminf(vl, vh));
            }
            #pragma unroll
            for (int r = 0; r < NRO; ++r) {     // prefetch step d+1
                const int i  = k0 + 128*r;
                const int lo = i - d - 1, hi = i + d + 1;
                plo[r] = (lo >= 0) ? si[lo*JTO + jj] : -1;
                phi[r] = (hi < HH) ? si[hi*JTO + jj] : -1;
            }
            mx = 0.f;
            #pragma unroll
            for (int r = 0; r < NRO; ++r) mx = fmaxf(mx, dout2[r]);
        }

        #pragma unroll
        for (int r = 0; r < NRO; ++r) {
            const int i = k0 + 128*r;
            const float p = g_prob[((b*CC + tc[r])*HH + i)*WW + j0 + jj];
            acc -= sqrtf(dout2[r]) * p;
        }
    }

    __syncthreads();
    block_reduce_write(acc, &g_part[blockIdx.x]);

    // ----- rendezvous: last block does the final reduction -----
    __shared__ int s_last;
    if (threadIdx.x == 0) {
        __threadfence();
        s_last = (atomicAdd(&g_sem, 1) == NCOL - 1) ? 1 : 0;
    }
    __syncthreads();
    if (!s_last) return;

    float v = 0.0f;
    for (int k = threadIdx.x; k < NCOL; k += 256)   // fixed order per thread
        v += g_part[k];
    #pragma unroll
    for (int o = 16; o > 0; o >>= 1)
        v += __shfl_xor_sync(0xffffffffu, v, o);
    __shared__ float fw[8];
    if ((threadIdx.x & 31) == 0) fw[threadIdx.x >> 5] = v;
    __syncthreads();
    if (threadIdx.x == 0) {
        float total = 0.f;
        #pragma unroll
        for (int w = 0; w < 8; ++w) total += fw[w];
        int n = 0;
        #pragma unroll
        for (int k = 0; k < BB*CC; ++k) n += (g_cnt[k] > 0) ? 1 : 0;
        const float nf = (n > 0) ? (float)n : 1.0f;
        out[0] = total / nf;
        // reset state for next graph replay
        #pragma unroll
        for (int k = 0; k < BB*CC; ++k) g_cnt[k] = 0;
        g_sem = 0;
    }
}

// ---------------------------------------------------------------------------
extern "C" void kernel_launch(void* const* d_in, const int* in_sizes, int n_in,
                              void* d_out, int out_size) {
    const float* output = (const float*)d_in[0];   // [4,8,256,256] fp32
    const int*   target = (const int*)d_in[1];     // [4,256,256] int32
    float*       out    = (float*)d_out;           // scalar

    k_pre<<<NROWB + NSMB, 256>>>(target, output);
    k_col<<<NCOL, 256>>>(out);
}